// round 17
// baseline (speedup 1.0000x reference)
#include <cuda_runtime.h>
#include <cuda_fp16.h>
#include <math.h>
#include <stdint.h>

#define BT   2048
#define TT   1024
#define DD   768
#define HH   12
#define HS   64
#define NKV  3
#define NL   12
#define II   2048
#define VV   50257
#define KVD  192
#define QKV  1152
#define GU   4096
#define EPS_ 1e-6f
#define WSC  1024.0f
#define OSC  (1.0f / 1024.0f)

// fp32 residual
__device__ float g_x[BT * DD];
// fp16 activations
__device__ __half g_qkv16[BT * QKV];   // qkv GEMM out (un-roped; V read in place)
__device__ __half g_h16[BT * DD];      // rmsnorm out
__device__ __half g_y16[BT * DD];      // attention out
__device__ __half g_a16[BT * II];      // silu*up out
__device__ __half g_q16[BT * DD];      // roped q (x 1/8)
__device__ __half g_k16[BT * KVD];     // roped k
// rope tables
__device__ float g_rs[TT * 32], g_rc[TT * 32];
// fp16 hi/lo weights x1024 ([K][N]; gu interleaved 2j=gate,2j+1=up)
__device__ __half s_qkvw_h[NL * DD * QKV], s_qkvw_l[NL * DD * QKV];
__device__ __half s_ow_h[NL * DD * DD],    s_ow_l[NL * DD * DD];
__device__ __half s_guw_h[NL * DD * GU],   s_guw_l[NL * DD * GU];
__device__ __half s_dw_h[NL * II * DD],    s_dw_l[NL * II * DD];
// fp16 single embed [V][K]
__device__ __half s_em[(size_t)VV * DD];

__device__ __forceinline__ void h16_split(float v, __half& h, __half& l) {
    v *= WSC;
    h = __float2half(v);
    l = __float2half(v - __half2float(h));
}
__device__ __forceinline__ uint32_t packh(__half a, __half b) {
    __half2 t = __halves2half2(a, b);
    return *(uint32_t*)&t;
}
__device__ __forceinline__ void ldmx4(uint32_t* r, uint32_t a) {
    asm volatile("ldmatrix.sync.aligned.m8n8.x4.shared.b16 {%0,%1,%2,%3}, [%4];"
                 : "=r"(r[0]), "=r"(r[1]), "=r"(r[2]), "=r"(r[3]) : "r"(a));
}
__device__ __forceinline__ void ldmx4t(uint32_t* r, uint32_t a) {
    asm volatile("ldmatrix.sync.aligned.m8n8.x4.trans.shared.b16 {%0,%1,%2,%3}, [%4];"
                 : "=r"(r[0]), "=r"(r[1]), "=r"(r[2]), "=r"(r[3]) : "r"(a));
}
__device__ __forceinline__ void mma16816h(float* c, const uint32_t* a, const uint32_t* b) {
    asm volatile("mma.sync.aligned.m16n8k16.row.col.f32.f16.f16.f32 "
                 "{%0,%1,%2,%3}, {%4,%5,%6,%7}, {%8,%9}, {%0,%1,%2,%3};"
                 : "+f"(c[0]), "+f"(c[1]), "+f"(c[2]), "+f"(c[3])
                 : "r"(a[0]), "r"(a[1]), "r"(a[2]), "r"(a[3]), "r"(b[0]), "r"(b[1]));
}
// fp16-accumulator variant (potential 2x rate on throttled legacy path)
__device__ __forceinline__ void mma16816hh(uint32_t& d0, uint32_t& d1,
                                           const uint32_t* a, const uint32_t* b) {
    asm volatile("mma.sync.aligned.m16n8k16.row.col.f16.f16.f16.f16 "
                 "{%0,%1}, {%2,%3,%4,%5}, {%6,%7}, {%0,%1};"
                 : "+r"(d0), "+r"(d1)
                 : "r"(a[0]), "r"(a[1]), "r"(a[2]), "r"(a[3]), "r"(b[0]), "r"(b[1]));
}
__device__ __forceinline__ void cpa16(uint32_t dst, const void* src) {
    asm volatile("cp.async.cg.shared.global [%0], [%1], 16;" :: "r"(dst), "l"(src));
}
__device__ __forceinline__ void cpcommit() { asm volatile("cp.async.commit_group;"); }
template<int N> __device__ __forceinline__ void cpwait() {
    asm volatile("cp.async.wait_group %0;" :: "n"(N));
}

// fp32 -> fp16 hi/lo (x1024)
__global__ void split16(const float* __restrict__ s, __half* __restrict__ h,
                        __half* __restrict__ l, int n4) {
    int i = blockIdx.x * 256 + threadIdx.x;
    if (i >= n4) return;
    float4 v = ((const float4*)s)[i];
    __half h0, h1, h2, h3, l0, l1, l2, l3;
    h16_split(v.x, h0, l0); h16_split(v.y, h1, l1);
    h16_split(v.z, h2, l2); h16_split(v.w, h3, l3);
    __half2* hp = (__half2*)(h + (size_t)i * 4);
    __half2* lp = (__half2*)(l + (size_t)i * 4);
    hp[0] = __halves2half2(h0, h1); hp[1] = __halves2half2(h2, h3);
    lp[0] = __halves2half2(l0, l1); lp[1] = __halves2half2(l2, l3);
}

// fp32 -> single fp16 (embed)
__global__ void conv16(const float* __restrict__ s, __half* __restrict__ h, int n4) {
    int i = blockIdx.x * 256 + threadIdx.x;
    if (i >= n4) return;
    float4 v = ((const float4*)s)[i];
    __half2* hp = (__half2*)(h + (size_t)i * 4);
    hp[0] = __halves2half2(__float2half(v.x), __float2half(v.y));
    hp[1] = __halves2half2(__float2half(v.z), __float2half(v.w));
}

// pack qkv weights -> [D][1152] fp16 hi/lo x1024
__global__ void pack_qkv16(const float* __restrict__ qw, const float* __restrict__ kw,
                           const float* __restrict__ vw) {
    int i4 = blockIdx.x * 256 + threadIdx.x;
    int c4 = (i4 % 288) * 4;
    int rl = i4 / 288;
    int row = rl % DD, l = rl / DD;
    const float* src;
    if (c4 < DD)            src = qw + ((size_t)l * DD + row) * DD + c4;
    else if (c4 < DD + KVD) src = kw + ((size_t)l * DD + row) * KVD + (c4 - DD);
    else                    src = vw + ((size_t)l * DD + row) * KVD + (c4 - DD - KVD);
    float4 v = *(const float4*)src;
    __half h0, h1, h2, h3, l0, l1, l2, l3;
    h16_split(v.x, h0, l0); h16_split(v.y, h1, l1);
    h16_split(v.z, h2, l2); h16_split(v.w, h3, l3);
    __half2* hp = (__half2*)(s_qkvw_h + (size_t)i4 * 4);
    __half2* lp = (__half2*)(s_qkvw_l + (size_t)i4 * 4);
    hp[0] = __halves2half2(h0, h1); hp[1] = __halves2half2(h2, h3);
    lp[0] = __halves2half2(l0, l1); lp[1] = __halves2half2(l2, l3);
}

// pack gate/up interleaved -> [D][4096] fp16 hi/lo x1024
__global__ void pack_gu16(const float* __restrict__ gw, const float* __restrict__ uw) {
    int i4 = blockIdx.x * 256 + threadIdx.x;
    int c4 = (i4 & 1023) * 4;
    int rl = i4 >> 10;
    int row = rl % DD, l = rl / DD;
    int j = c4 >> 1;
    float2 gv = *(const float2*)(gw + ((size_t)l * DD + row) * II + j);
    float2 uv = *(const float2*)(uw + ((size_t)l * DD + row) * II + j);
    float4 v = make_float4(gv.x, uv.x, gv.y, uv.y);
    __half h0, h1, h2, h3, l0, l1, l2, l3;
    h16_split(v.x, h0, l0); h16_split(v.y, h1, l1);
    h16_split(v.z, h2, l2); h16_split(v.w, h3, l3);
    __half2* hp = (__half2*)(s_guw_h + (size_t)i4 * 4);
    __half2* lp = (__half2*)(s_guw_l + (size_t)i4 * 4);
    hp[0] = __halves2half2(h0, h1); hp[1] = __halves2half2(h2, h3);
    lp[0] = __halves2half2(l0, l1); lp[1] = __halves2half2(l2, l3);
}

// rope tables
__global__ void rope_table() {
    int t = blockIdx.x, d = threadIdx.x;
    float freq = powf(10000.f, (float)d / 32.0f);
    float s, c;
    sincosf((float)t / freq, &s, &c);
    g_rs[t * 32 + d] = s;
    g_rc[t * 32 + d] = c;
}

__global__ void embed_kernel(const int* __restrict__ idx, const float* __restrict__ embed) {
    int row = blockIdx.x;
    const float4* src = (const float4*)(embed + (size_t)idx[row] * DD);
    ((float4*)(g_x + (size_t)row * DD))[threadIdx.x] = src[threadIdx.x];
}

// RMSNorm -> single fp16
__global__ __launch_bounds__(256) void rmsnorm16(const float* __restrict__ in,
                                                 const float* __restrict__ w,
                                                 __half* __restrict__ o) {
    int row = blockIdx.x;
    const float* x = in + (size_t)row * DD;
    float s = 0.f;
    for (int i = threadIdx.x; i < DD; i += 256) { float v = x[i]; s += v * v; }
    #pragma unroll
    for (int of = 16; of; of >>= 1) s += __shfl_xor_sync(0xffffffffu, s, of);
    __shared__ float red[8];
    if ((threadIdx.x & 31) == 0) red[threadIdx.x >> 5] = s;
    __syncthreads();
    if (threadIdx.x < 8) {
        s = red[threadIdx.x];
        #pragma unroll
        for (int of = 4; of; of >>= 1) s += __shfl_xor_sync(0xffu, s, of);
        if (threadIdx.x == 0) red[0] = s;
    }
    __syncthreads();
    float inv = rsqrtf(red[0] / (float)DD + EPS_);
    for (int i = threadIdx.x; i < DD; i += 256)
        o[(size_t)row * DD + i] = __float2half(w[i] * x[i] * inv);
}

// ---------------- fp16 mma.sync GEMM, 3-stage cp.async pipeline ----------------
// TERMS=2: C = (A @ (Bh+Bl)) * 1/1024 (B x1024); lo-term via fp16-accum MMA + fold.
// TERMS=1: C = A @ Bh. TRANSB: B[N,K]. SPLITK: K-range + fp32 atomicAdd.
// MSWAP: m fast. SILU: gate/up interleaved -> silu(g)*u -> g_a16. OUT16: C is __half*.
template<int TRANSB, int SPLITK, int MSWAP, int SILU, int TERMS, int OUT16>
__global__ __launch_bounds__(256) void hgemm(const __half* __restrict__ A,
                                             const __half* __restrict__ Bh,
                                             const __half* __restrict__ Bl,
                                             float* __restrict__ C,
                                             int M, int N, int K) {
    constexpr int AST   = 40;
    constexpr int BROWS = TRANSB ? 128 : 32;
    constexpr int BST   = TRANSB ? 40  : 136;
    constexpr int ASZ   = 128 * AST;
    constexpr int BSZ   = BROWS * BST;
    constexpr int STG   = ASZ + TERMS * BSZ;
    constexpr int NSTG  = 3;

    extern __shared__ __half smem[];
    int tid  = threadIdx.x;
    int lane = tid & 31, wid = tid >> 5;
    int wm = wid >> 2, wn = wid & 3;
    int row0 = (MSWAP ? blockIdx.x : blockIdx.y) * 128;
    int col0 = (MSWAP ? blockIdx.y : blockIdx.x) * 128;
    int kbeg = 0, klen = K;
    if (SPLITK > 1) {
        int kb = ((K / SPLITK) / 32) * 32;
        kbeg = blockIdx.z * kb;
        klen = (blockIdx.z == SPLITK - 1) ? (K - kb * (SPLITK - 1)) : kb;
    }

    float c[4][4][4] = {};
    uint32_t sbase = (uint32_t)__cvta_generic_to_shared(smem);
    int am = tid >> 2, aq = (tid & 3) * 8;

    auto load_stage = [&](int st, int k0) {
        uint32_t aoff = sbase + (uint32_t)st * STG * 2;
        #pragma unroll
        for (int i = 0; i < 2; i++) {
            int m = am + i * 64;
            cpa16(aoff + (m * AST + aq) * 2, A + (size_t)(row0 + m) * K + k0 + aq);
        }
        uint32_t boff = aoff + ASZ * 2;
        if (!TRANSB) {
            #pragma unroll
            for (int i = 0; i < 2; i++) {
                int k = (tid >> 4) + i * 16, q = (tid & 15) * 8;
                size_t g = (size_t)(k0 + k) * N + col0 + q;
                cpa16(boff + (k * BST + q) * 2, Bh + g);
                if (TERMS == 2) cpa16(boff + (BSZ + k * BST + q) * 2, Bl + g);
            }
        } else {
            #pragma unroll
            for (int i = 0; i < 2; i++) {
                int n = (tid >> 2) + i * 64, q = (tid & 3) * 8;
                if (col0 + n < N) {
                    size_t g = (size_t)(col0 + n) * K + k0 + q;
                    cpa16(boff + (n * BST + q) * 2, Bh + g);
                    if (TERMS == 2) cpa16(boff + (BSZ + n * BST + q) * 2, Bl + g);
                }
            }
        }
    };

    int nit = klen / 32;
    load_stage(0, kbeg);      cpcommit();
    load_stage(1, kbeg + 32); cpcommit();

    for (int it = 0; it < nit; it++) {
        int j = it + 2;
        if (j < nit)           { load_stage(j % NSTG, kbeg + j * 32); cpcommit(); cpwait<2>(); }
        else if (it + 1 < nit) { cpwait<1>(); }
        else                   { cpwait<0>(); }
        __syncthreads();

        int cur = it % NSTG;
        uint32_t sA   = sbase + (uint32_t)cur * STG * 2;
        uint32_t sB   = sA + ASZ * 2;
        uint32_t sBl_ = sB + BSZ * 2;

        #pragma unroll
        for (int kk = 0; kk < 32; kk += 16) {
            uint32_t fah[4][4], fbh[2][4], fbl[2][4];
            int abase = ((wm * 64 + (lane & 15)) * AST + (lane >> 4) * 8 + kk) * 2;
            #pragma unroll
            for (int mf = 0; mf < 4; mf++)
                ldmx4(fah[mf], sA + abase + mf * 16 * AST * 2);
            if (!TRANSB) {
                int bbase = (((lane & 7) + ((lane >> 3) & 1) * 8 + kk) * BST
                             + wn * 32 + ((lane >> 4) & 1) * 8) * 2;
                ldmx4t(fbh[0], sB + bbase);   ldmx4t(fbh[1], sB + bbase + 32);
                if (TERMS == 2) { ldmx4t(fbl[0], sBl_ + bbase); ldmx4t(fbl[1], sBl_ + bbase + 32); }
            } else {
                int bbase = ((wn * 32 + (lane & 7) + ((lane >> 4) & 1) * 8) * BST
                             + ((lane >> 3) & 1) * 8 + kk) * 2;
                ldmx4(fbh[0], sB + bbase);   ldmx4(fbh[1], sB + bbase + 16 * BST * 2);
                if (TERMS == 2) { ldmx4(fbl[0], sBl_ + bbase); ldmx4(fbl[1], sBl_ + bbase + 16 * BST * 2); }
            }
            #pragma unroll
            for (int mf = 0; mf < 4; mf++)
                #pragma unroll
                for (int nf = 0; nf < 4; nf++) {
                    mma16816h(c[mf][nf], fah[mf], &fbh[nf >> 1][(nf & 1) * 2]);
                    if (TERMS == 2) {
                        // lo term: fp16-accum MMA (zero-init), fold to fp32
                        uint32_t d0 = 0, d1 = 0;
                        mma16816hh(d0, d1, fah[mf], &fbl[nf >> 1][(nf & 1) * 2]);
                        float2 v0 = __half22float2(*(__half2*)&d0);
                        float2 v1 = __half22float2(*(__half2*)&d1);
                        c[mf][nf][0] += v0.x; c[mf][nf][1] += v0.y;
                        c[mf][nf][2] += v1.x; c[mf][nf][3] += v1.y;
                    }
                }
        }
        __syncthreads();
    }

    const float osc = (TERMS == 2) ? OSC : 1.0f;
    int g = lane >> 2, t = lane & 3;
    #pragma unroll
    for (int mf = 0; mf < 4; mf++) {
        #pragma unroll
        for (int nf = 0; nf < 4; nf++) {
            int r  = row0 + wm * 64 + mf * 16 + g;
            int cc = col0 + wn * 32 + nf * 8 + t * 2;
            if (SILU) {
                int j = cc >> 1;
                float g0 = c[mf][nf][0] * OSC, u0 = c[mf][nf][1] * OSC;
                float g1 = c[mf][nf][2] * OSC, u1 = c[mf][nf][3] * OSC;
                g_a16[(size_t)r * II + j]       = __float2half(g0 / (1.f + __expf(-g0)) * u0);
                g_a16[(size_t)(r + 8) * II + j] = __float2half(g1 / (1.f + __expf(-g1)) * u1);
            } else if (OUT16) {
                __half* H = (__half*)C;
                *(__half2*)&H[(size_t)r * N + cc] = __halves2half2(
                    __float2half(c[mf][nf][0] * osc), __float2half(c[mf][nf][1] * osc));
                *(__half2*)&H[(size_t)(r + 8) * N + cc] = __halves2half2(
                    __float2half(c[mf][nf][2] * osc), __float2half(c[mf][nf][3] * osc));
            } else if (SPLITK > 1) {
                float* p0 = C + (size_t)r * N + cc;
                float* p1 = C + (size_t)(r + 8) * N + cc;
                atomicAdd(p0,     c[mf][nf][0] * osc); atomicAdd(p1,     c[mf][nf][2] * osc);
                atomicAdd(p0 + 1, c[mf][nf][1] * osc); atomicAdd(p1 + 1, c[mf][nf][3] * osc);
            } else {
                float* p0 = C + (size_t)r * N + cc;
                float* p1 = C + (size_t)(r + 8) * N + cc;
                if (cc < N)     { p0[0] = c[mf][nf][0] * osc; p1[0] = c[mf][nf][2] * osc; }
                if (cc + 1 < N) { p0[1] = c[mf][nf][1] * osc; p1[1] = c[mf][nf][3] * osc; }
            }
        }
    }
}

// fused RoPE (table-based): q -> g_q16 (x1/8), k -> g_k16. V stays in g_qkv16.
__global__ void rope16() {
    int row = blockIdx.x;
    int t = row % TT;
    int i = threadIdx.x;                  // 480 = 15 heads * 32
    int head = i >> 5, d = i & 31;
    float s = g_rs[t * 32 + d], c = g_rc[t * 32 + d];
    if (head < HH) {
        size_t base = (size_t)row * QKV + head * HS;
        float xr = __half2float(g_qkv16[base + d]);
        float xi = __half2float(g_qkv16[base + d + 32]);
        size_t ob = (size_t)row * DD + head * HS;
        g_q16[ob + d]      = __float2half((xr * c - xi * s) * 0.125f);
        g_q16[ob + d + 32] = __float2half((xi * c + xr * s) * 0.125f);
    } else {
        int kh = head - HH;
        size_t base = (size_t)row * QKV + DD + kh * HS;
        float xr = __half2float(g_qkv16[base + d]);
        float xi = __half2float(g_qkv16[base + d + 32]);
        size_t ob = (size_t)row * KVD + kh * HS;
        g_k16[ob + d]      = __float2half(xr * c - xi * s);
        g_k16[ob + d + 32] = __float2half(xi * c + xr * s);
    }
}

// flash attention, all-fp16 single-plane, 128-query tiles, reversed CTA order
#define AT_ST 72
#define ATN_SMEM ((128 * AT_ST + 2 * 64 * AT_ST) * 2)   // 36864 B
__global__ __launch_bounds__(256) void attn_mma() {
    extern __shared__ __half sm[];
    __half* Qs = sm;
    __half* Ks = Qs + 128 * AT_ST;
    __half* Vs = Ks + 64 * AT_ST;
    int tid = threadIdx.x, lane = tid & 31, w = tid >> 5;
    int q0 = (gridDim.x - 1 - blockIdx.x) * 128;     // heavy CTAs first
    int b = blockIdx.y / HH, h = blockIdx.y % HH, kvh = h % NKV;
    uint32_t sQ = (uint32_t)__cvta_generic_to_shared(Qs);
    uint32_t sK = (uint32_t)__cvta_generic_to_shared(Ks);
    uint32_t sV = (uint32_t)__cvta_generic_to_shared(Vs);

    for (int i = tid; i < 128 * 8; i += 256) {
        int row = i >> 3, q8 = (i & 7) * 8;
        *(uint4*)&Qs[row * AT_ST + q8] =
            *(const uint4*)&g_q16[(size_t)(b * TT + q0 + row) * DD + h * HS + q8];
    }
    __syncthreads();
    uint32_t qf[4][4];
    {
        int abase = ((w * 16 + (lane & 15)) * AT_ST + (lane >> 4) * 8) * 2;
        #pragma unroll
        for (int kp = 0; kp < 4; kp++)
            ldmx4(qf[kp], sQ + abase + kp * 32);
    }
    float m0 = -1e30f, m1 = -1e30f, l0 = 0.f, l1 = 0.f;
    float co[8][4] = {};
    int r_seq = q0 + w * 16 + (lane >> 2);
    int nt = q0 / 64 + 2;

    for (int it = 0; it < nt; it++) {
        int s0 = it * 64;
        __syncthreads();
        for (int i = tid; i < 64 * 8; i += 256) {
            int row = i >> 3, q8 = (i & 7) * 8;
            *(uint4*)&Ks[row * AT_ST + q8] =
                *(const uint4*)&g_k16[(size_t)(b * TT + s0 + row) * KVD + kvh * HS + q8];
            *(uint4*)&Vs[row * AT_ST + q8] =
                *(const uint4*)&g_qkv16[(size_t)(b * TT + s0 + row) * QKV + DD + KVD + kvh * HS + q8];
        }
        __syncthreads();
        float cs[8][4] = {};
        #pragma unroll
        for (int kp = 0; kp < 4; kp++) {
            #pragma unroll
            for (int ng = 0; ng < 4; ng++) {
                uint32_t bk[4];
                int bbase = ((ng * 16 + (lane & 7) + ((lane >> 4) & 1) * 8) * AT_ST
                             + ((lane >> 3) & 1) * 8 + kp * 16) * 2;
                ldmx4(bk, sK + bbase);
                mma16816h(cs[2 * ng],     qf[kp], &bk[0]);
                mma16816h(cs[2 * ng + 1], qf[kp], &bk[2]);
            }
        }
        if (s0 + 63 > q0 + w * 16) {
            #pragma unroll
            for (int nf = 0; nf < 8; nf++) {
                int key = s0 + nf * 8 + (lane & 3) * 2;
                if (key     > r_seq)     cs[nf][0] = -1e30f;
                if (key + 1 > r_seq)     cs[nf][1] = -1e30f;
                if (key     > r_seq + 8) cs[nf][2] = -1e30f;
                if (key + 1 > r_seq + 8) cs[nf][3] = -1e30f;
            }
        }
        float mx0 = cs[0][0], mx1 = cs[0][2];
        #pragma unroll
        for (int nf = 0; nf < 8; nf++) {
            mx0 = fmaxf(mx0, fmaxf(cs[nf][0], cs[nf][1]));
            mx1 = fmaxf(mx1, fmaxf(cs[nf][2], cs[nf][3]));
        }
        mx0 = fmaxf(mx0, __shfl_xor_sync(0xffffffffu, mx0, 1));
        mx0 = fmaxf(mx0, __shfl_xor_sync(0xffffffffu, mx0, 2));
        mx1 = fmaxf(mx1, __shfl_xor_sync(0xffffffffu, mx1, 1));
        mx1 = fmaxf(mx1, __shfl_xor_sync(0xffffffffu, mx1, 2));
        float nm0 = fmaxf(m0, mx0), nm1 = fmaxf(m1, mx1);
        float corr0 = __expf(m0 - nm0), corr1 = __expf(m1 - nm1);
        m0 = nm0; m1 = nm1;
        uint32_t pf[4][4];
        float sum0 = 0.f, sum1 = 0.f;
        #pragma unroll
        for (int nf = 0; nf < 8; nf++) {
            float p0 = __expf(cs[nf][0] - nm0), p1 = __expf(cs[nf][1] - nm0);
            float p2 = __expf(cs[nf][2] - nm1), p3 = __expf(cs[nf][3] - nm1);
            sum0 += p0 + p1; sum1 += p2 + p3;
            int kp = nf >> 1, o = (nf & 1) * 2;
            pf[kp][o]     = packh(__float2half(p0), __float2half(p1));
            pf[kp][o + 1] = packh(__float2half(p2), __float2half(p3));
        }
        sum0 += __shfl_xor_sync(0xffffffffu, sum0, 1);
        sum0 += __shfl_xor_sync(0xffffffffu, sum0, 2);
        sum1 += __shfl_xor_sync(0xffffffffu, sum1, 1);
        sum1 += __shfl_xor_sync(0xffffffffu, sum1, 2);
        l0 = l0 * corr0 + sum0;
        l1 = l1 * corr1 + sum1;
        #pragma unroll
        for (int nf = 0; nf < 8; nf++) {
            co[nf][0] *= corr0; co[nf][1] *= corr0;
            co[nf][2] *= corr1; co[nf][3] *= corr1;
        }
        #pragma unroll
        for (int kp = 0; kp < 4; kp++) {
            #pragma unroll
            for (int ng = 0; ng < 4; ng++) {
                uint32_t bv[4];
                int bbase = (((lane & 7) + ((lane >> 3) & 1) * 8 + kp * 16) * AT_ST
                             + ng * 16 + ((lane >> 4) & 1) * 8) * 2;
                ldmx4t(bv, sV + bbase);
                mma16816h(co[2 * ng],     pf[kp], &bv[0]);
                mma16816h(co[2 * ng + 1], pf[kp], &bv[2]);
            }
        }
    }
    float il0 = 1.f / l0, il1 = 1.f / l1;
    size_t base0 = (size_t)(b * TT + r_seq) * DD + h * HS;
    size_t base1 = base0 + (size_t)8 * DD;
    #pragma unroll
    for (int nf = 0; nf < 8; nf++) {
        int cc = nf * 8 + (lane & 3) * 2;
        *(__half2*)&g_y16[base0 + cc] = __halves2half2(
            __float2half(co[nf][0] * il0), __float2half(co[nf][1] * il0));
        *(__half2*)&g_y16[base1 + cc] = __halves2half2(
            __float2half(co[nf][2] * il1), __float2half(co[nf][3] * il1));
    }
}

static inline int sgrid(size_t n4) { return (int)((n4 + 255) / 256); }

extern "C" void kernel_launch(void* const* d_in, const int* in_sizes, int n_in,
                              void* d_out, int out_size) {
    const int*   idx   = (const int*)d_in[0];
    const float* embed = (const float*)d_in[1];
    const float* ln1   = (const float*)d_in[2];
    const float* qw    = (const float*)d_in[3];
    const float* kw    = (const float*)d_in[4];
    const float* vw    = (const float*)d_in[5];
    const float* ow    = (const float*)d_in[6];
    const float* ln2   = (const float*)d_in[7];
    const float* gw    = (const float*)d_in[8];
    const float* uw    = (const float*)d_in[9];
    const float* dw    = (const float*)d_in[10];
    const float* nw    = (const float*)d_in[11];
    float* out = (float*)d_out;

    float* px;
    cudaGetSymbolAddress((void**)&px, g_x);
    __half *h16, *y16, *a16, *qkv16;
    cudaGetSymbolAddress((void**)&h16, g_h16);
    cudaGetSymbolAddress((void**)&y16, g_y16);
    cudaGetSymbolAddress((void**)&a16, g_a16);
    cudaGetSymbolAddress((void**)&qkv16, g_qkv16);
    __half *qkvwh, *qkvwl, *owh, *owl, *guwh, *guwl, *dwh, *dwl, *em;
    cudaGetSymbolAddress((void**)&qkvwh, s_qkvw_h); cudaGetSymbolAddress((void**)&qkvwl, s_qkvw_l);
    cudaGetSymbolAddress((void**)&owh, s_ow_h);     cudaGetSymbolAddress((void**)&owl, s_ow_l);
    cudaGetSymbolAddress((void**)&guwh, s_guw_h);   cudaGetSymbolAddress((void**)&guwl, s_guw_l);
    cudaGetSymbolAddress((void**)&dwh, s_dw_h);     cudaGetSymbolAddress((void**)&dwl, s_dw_l);
    cudaGetSymbolAddress((void**)&em,  s_em);

    const int SM_G0 = 3 * (128 * 40 + 2 * 32 * 136) * 2;    // 82944 B (TERMS=2)
    const int SM_G1 = 3 * (128 * 40 + 128 * 40) * 2;        // 61440 B (TERMS=1, TRANSB=1)
    cudaFuncSetAttribute(hgemm<0, 1, 0, 0, 2, 1>, cudaFuncAttributeMaxDynamicSharedMemorySize, SM_G0);
    cudaFuncSetAttribute(hgemm<0, 3, 0, 0, 2, 0>, cudaFuncAttributeMaxDynamicSharedMemorySize, SM_G0);
    cudaFuncSetAttribute(hgemm<0, 1, 0, 1, 2, 0>, cudaFuncAttributeMaxDynamicSharedMemorySize, SM_G0);
    cudaFuncSetAttribute(hgemm<1, 1, 1, 0, 1, 0>, cudaFuncAttributeMaxDynamicSharedMemorySize, SM_G1);
    cudaFuncSetAttribute(attn_mma, cudaFuncAttributeMaxDynamicSharedMemorySize, ATN_SMEM);

    // prologue
    pack_qkv16<<<NL * DD * 288 / 256, 256>>>(qw, kw, vw);
    pack_gu16 <<<NL * DD * 1024 / 256, 256>>>(gw, uw);
    split16<<<sgrid((size_t)NL * DD * DD / 4), 256>>>(ow, owh, owl, NL * DD * DD / 4);
    split16<<<sgrid((size_t)NL * II * DD / 4), 256>>>(dw, dwh, dwl, NL * II * DD / 4);
    conv16<<<sgrid((size_t)VV * DD / 4), 256>>>(embed, em, VV * DD / 4);
    rope_table<<<TT, 32>>>();

    dim3 gqkv(QKV / 128, BT / 128);           // (9,16)
    dim3 go(DD / 128, BT / 128, 3);           // (6,16,3) split-K=3
    dim3 ggu(GU / 128, BT / 128);             // (32,16) silu-fused
    dim3 ga(TT / 128, 2 * HH);                // (8,24)
    dim3 gl(BT / 128, (VV + 127) / 128);      // MSWAP: x=m(16), y=n(393)

    embed_kernel<<<BT, 192>>>(idx, embed);

    for (int l = 0; l < NL; l++) {
        size_t oQ  = (size_t)l * DD * QKV;
        size_t oO  = (size_t)l * DD * DD;
        size_t oG  = (size_t)l * DD * GU;
        size_t oD2 = (size_t)l * II * DD;
        rmsnorm16<<<BT, 256>>>(px, ln1 + (size_t)l * DD, h16);
        hgemm<0, 1, 0, 0, 2, 1><<<gqkv, 256, SM_G0>>>(h16, qkvwh + oQ, qkvwl + oQ,
                                                      (float*)qkv16, BT, QKV, DD);
        rope16<<<BT, 480>>>();
        attn_mma<<<ga, 256, ATN_SMEM>>>();
        hgemm<0, 3, 0, 0, 2, 0><<<go, 256, SM_G0>>>(y16, owh + oO, owl + oO, px, BT, DD, DD);
        rmsnorm16<<<BT, 256>>>(px, ln2 + (size_t)l * DD, h16);
        hgemm<0, 1, 0, 1, 2, 0><<<ggu, 256, SM_G0>>>(h16, guwh + oG, guwl + oG, px, BT, GU, DD);
        hgemm<0, 3, 0, 0, 2, 0><<<go, 256, SM_G0>>>(a16, dwh + oD2, dwl + oD2, px, BT, DD, II);
    }
    rmsnorm16<<<BT, 256>>>(px, nw, h16);
    hgemm<1, 1, 1, 0, 1, 0><<<gl, 256, SM_G1>>>(h16, em, em, out, BT, VV, DD);
}